// round 2
// baseline (speedup 1.0000x reference)
#include <cuda_runtime.h>

// Bilinear flow warp:
//   img: [B=8, C=16, H=512, W=512] f32
//   flo: [B=8, 2,   H=512, W=512] f32  (ch0 = x disp, ch1 = y disp)
//   out: [B=8, C=16, H=512, W=512] f32
//
// One thread per (b,h,w) pixel. Per channel, each gather row (y0, y1) is
// fetched with ONE aligned LDG.128 at (x0 & ~3), which contains both x0 and
// x1 = x0+1 for the 75% of lanes where x0 % 4 != 3; a predicated scalar LDG
// covers the rest. This cuts L1 wavefronts vs 4 scalar gathers/channel.

#define B_ 8
#define C_ 16
#define H_ 512
#define W_ 512
#define HW_ (H_ * W_)

__device__ __forceinline__ float sel4(float4 f, int j) {
    // j in [0,3]
    float lo = (j == 0) ? f.x : f.y;
    float hi = (j == 2) ? f.z : f.w;
    return (j < 2) ? lo : hi;
}

__global__ __launch_bounds__(256) void warp_bilinear_kernel(
    const float* __restrict__ img,
    const float* __restrict__ flo,
    float* __restrict__ out)
{
    int idx = blockIdx.x * blockDim.x + threadIdx.x;  // over B*H*W = 2,097,152
    if (idx >= B_ * HW_) return;

    int w  = idx & (W_ - 1);
    int t  = idx >> 9;          // b*H + h
    int h  = t & (H_ - 1);
    int b  = t >> 9;

    // flo layout [B,2,H,W]
    int flo_base = ((b * 2) * H_ + h) * W_ + w;
    float fx = __ldg(flo + flo_base);
    float fy = __ldg(flo + flo_base + HW_);

    float px = (float)w + fx;
    float py = (float)h + fy;

    float x0f = floorf(px);
    float y0f = floorf(py);
    float xw  = px - x0f;       // weights from UNclamped floor (matches reference)
    float yw  = py - y0f;

    int x0 = (int)fminf(fmaxf(x0f,        0.0f), (float)(W_ - 1));
    int x1 = (int)fminf(fmaxf(x0f + 1.0f, 0.0f), (float)(W_ - 1));
    int y0 = (int)fminf(fmaxf(y0f,        0.0f), (float)(H_ - 1));
    int y1 = (int)fminf(fmaxf(y0f + 1.0f, 0.0f), (float)(H_ - 1));

    float wa = (1.0f - xw) * (1.0f - yw);
    float wb = (1.0f - xw) * yw;
    float wc = xw * (1.0f - yw);
    float wd = xw * yw;

    // Aligned 4-float window containing x0 (and x1 unless j1 > 3).
    int xa = x0 & ~3;
    int j0 = x0 - xa;           // [0,3]
    int j1 = x1 - xa;           // [0,4]  (== j0 at right/left border where x1==x0)
    bool needx = (j1 > 3);      // only when x0 % 4 == 3 and x1 == x0 + 1
    int j1c = needx ? 3 : j1;   // safe select index (value overridden when needx)

    int row0 = y0 * W_ + xa;
    int row1 = y1 * W_ + xa;
    int ex0  = y0 * W_ + x1;
    int ex1  = y1 * W_ + x1;

    const float* ibase = img + (size_t)b * C_ * HW_;
    float*       obase = out + (size_t)b * C_ * HW_ + h * W_ + w;

    #pragma unroll
    for (int c = 0; c < C_; c++) {
        const float* p = ibase + c * HW_;

        float4 fa = __ldg((const float4*)(p + row0));   // row y0: xa..xa+3
        float4 fb = __ldg((const float4*)(p + row1));   // row y1: xa..xa+3

        float ea = 0.0f, eb = 0.0f;
        if (needx) {
            ea = __ldg(p + ex0);
            eb = __ldg(p + ex1);
        }

        float Ia = sel4(fa, j0);
        float Ib = sel4(fb, j0);
        float Ic = needx ? ea : sel4(fa, j1c);
        float Id = needx ? eb : sel4(fb, j1c);

        obase[c * HW_] = wa * Ia + wb * Ib + wc * Ic + wd * Id;
    }
}

extern "C" void kernel_launch(void* const* d_in, const int* in_sizes, int n_in,
                              void* d_out, int out_size)
{
    const float* img = (const float*)d_in[0];
    const float* flo = (const float*)d_in[1];
    float* out = (float*)d_out;

    const int total = B_ * HW_;           // 2,097,152 pixels
    const int threads = 256;
    const int blocks = (total + threads - 1) / threads;  // 8192
    warp_bilinear_kernel<<<blocks, threads>>>(img, flo, out);
}

// round 3
// speedup vs baseline: 1.3139x; 1.3139x over previous
#include <cuda_runtime.h>

// Bilinear flow warp via full-width SMEM row strips.
//   img: [B=8, C=16, H=512, W=512] f32
//   flo: [B=8, 2,   H=512, W=512] f32
//   out: [B=8, C=16, H=512, W=512] f32
//
// Block = one (b, 8-row) strip of full width 512. Per channel, 16 rows
// (8 + 4 halo each side) are staged in SMEM with coalesced float4 loads;
// bilinear gathers then hit SMEM (bank-addressed, no line-split cost).
// x-clamp stays inside resident rows (full width); y beyond the halo
// (P ~ 6e-5) falls back to predicated global gathers.

#define B_    8
#define C_    16
#define H_    512
#define W_    512
#define HW_   (H_ * W_)
#define TY    8
#define HALO  4
#define TROWS (TY + 2 * HALO)   // 16
#define THREADS 512

__global__ __launch_bounds__(THREADS, 2) void warp_bilinear_kernel(
    const float* __restrict__ img,
    const float* __restrict__ flo,
    float* __restrict__ out)
{
    __shared__ float tile[TROWS * W_];   // 32 KB

    const int bx = blockIdx.x;           // 0 .. B_*(H_/TY)-1 = 511
    const int b  = bx >> 6;              // H_/TY = 64 strips per batch
    const int h0 = (bx & 63) * TY;
    const int w  = threadIdx.x;          // 0..511, one column per thread

    // ---- Prologue: per-pixel geometry (channel-invariant), cached in regs ----
    float xw[TY], yw[TY];
    int   pk[TY];                        // x0 | y0<<10 | dx<<20 | dy<<21 | fb<<22

    const int flo_b = (b * 2) * HW_;
    #pragma unroll
    for (int i = 0; i < TY; i++) {
        int h = h0 + i;
        float fx = __ldg(flo + flo_b + h * W_ + w);
        float fy = __ldg(flo + flo_b + HW_ + h * W_ + w);

        float px = (float)w + fx;
        float py = (float)h + fy;
        float x0f = floorf(px);
        float y0f = floorf(py);
        xw[i] = px - x0f;                // weights from UNclamped floor
        yw[i] = py - y0f;

        int x0 = (int)fminf(fmaxf(x0f,        0.0f), (float)(W_ - 1));
        int x1 = (int)fminf(fmaxf(x0f + 1.0f, 0.0f), (float)(W_ - 1));
        int y0 = (int)fminf(fmaxf(y0f,        0.0f), (float)(H_ - 1));
        int y1 = (int)fminf(fmaxf(y0f + 1.0f, 0.0f), (float)(H_ - 1));

        int dx = x1 - x0;                // 0 or 1
        int dy = y1 - y0;                // 0 or 1
        int fb = (y0 < h0 - HALO) || (y1 > h0 + TY - 1 + HALO);
        pk[i] = x0 | (y0 << 10) | (dx << 20) | (dy << 21) | (fb << 22);
    }

    const int row_lo = h0 - HALO;        // first tile row (global, may be <0)

    for (int c = 0; c < C_; c++) {
        const float* plane = img + ((size_t)(b * C_ + c)) * HW_;

        __syncthreads();                 // protect tile from previous channel
        // ---- Fill: 2048 float4 = 16 rows x 512 floats, coalesced ----
        #pragma unroll
        for (int k = 0; k < 4; k++) {
            int f   = threadIdx.x + k * THREADS;   // float4 index 0..2047
            int r   = f >> 7;                      // 128 float4 per row
            int col = (f & 127) << 2;
            int gy  = min(max(row_lo + r, 0), H_ - 1);
            float4 v = __ldg((const float4*)(plane + gy * W_ + col));
            *(float4*)&tile[r * W_ + col] = v;
        }
        __syncthreads();

        // ---- Gather + blend + store for my 8 pixels ----
        float* oplane = out + ((size_t)(b * C_ + c)) * HW_;
        #pragma unroll
        for (int i = 0; i < TY; i++) {
            int p  = pk[i];
            int x0 = p & 1023;
            int y0 = (p >> 10) & 1023;
            int dx = (p >> 20) & 1;
            int dy = (p >> 21) & 1;

            float Ia, Ib, Ic, Id;
            if (!(p >> 22)) {
                int base  = (y0 - row_lo) * W_ + x0;
                int base1 = base + dy * W_;
                Ia = tile[base];
                Ic = tile[base + dx];
                Ib = tile[base1];
                Id = tile[base1 + dx];
            } else {
                const float* g  = plane + y0 * W_ + x0;
                const float* g1 = g + dy * W_;
                Ia = __ldg(g);
                Ic = __ldg(g + dx);
                Ib = __ldg(g1);
                Id = __ldg(g1 + dx);
            }

            float xwv = xw[i], ywv = yw[i];
            float wa = (1.0f - xwv) * (1.0f - ywv);
            float wb = (1.0f - xwv) * ywv;
            float wc = xwv * (1.0f - ywv);
            float wd = xwv * ywv;

            float r = wa * Ia;
            r = fmaf(wb, Ib, r);
            r = fmaf(wc, Ic, r);
            r = fmaf(wd, Id, r);
            oplane[(h0 + i) * W_ + w] = r;
        }
    }
}

extern "C" void kernel_launch(void* const* d_in, const int* in_sizes, int n_in,
                              void* d_out, int out_size)
{
    const float* img = (const float*)d_in[0];
    const float* flo = (const float*)d_in[1];
    float* out = (float*)d_out;

    const int blocks = B_ * (H_ / TY);   // 512
    warp_bilinear_kernel<<<blocks, THREADS>>>(img, flo, out);
}